// round 1
// baseline (speedup 1.0000x reference)
#include <cuda_runtime.h>
#include <math.h>

#define B 64
#define LS 256
#define M 4
#define LW 256
#define LY 128
#define HID 512
#define NSTEP 6

// ---------------- scratch (__device__ globals: no allocs allowed) ----------
__device__ float d_phi[B*LS];
__device__ float d_sre[B*LS];
__device__ float d_sim[B*LS];
__device__ float d_Gsr[B*LS*M];
__device__ float d_Gsi[B*LS*M];
__device__ float d_Hsr[B*LS*M];
__device__ float d_Hsi[B*LS*M];
__device__ float d_sGr[B*M];
__device__ float d_sGi[B*M];
__device__ float d_sHr[B*M];
__device__ float d_sHi[B*M];
__device__ float d_hs[B*HID];
__device__ float d_wyW[B*M*HID];
__device__ float d_rho[B*M];
__device__ float d_mu[M*HID];
__device__ float d_scale[M*HID];

// ---------------- init: working copy of phi --------------------------------
__global__ void k_init(const float* __restrict__ phi) {
    int idx = blockIdx.x * LS + threadIdx.x;
    d_phi[idx] = phi[idx];
}

// ---------------- precompute wy @ W1[512:] + b1  (step-invariant) ----------
__global__ void k_wyW(const float* __restrict__ wr, const float* __restrict__ wi,
                      const float* __restrict__ y,  const float* __restrict__ W1,
                      const float* __restrict__ b1) {
    int m = blockIdx.x, b = blockIdx.y;
    int tid = threadIdx.x;                 // h
    __shared__ float wy[2*LW + LY];        // 640
    for (int d = tid; d < 2*LW + LY; d += HID) {
        float v;
        if (d < LW)            v = wr[(b*LW + d)*M + m];
        else if (d < 2*LW)     v = wi[(b*LW + (d - LW))*M + m];
        else                   v = y [(b*LY + (d - 2*LW))*M + m];
        wy[d] = v;
    }
    __syncthreads();
    float acc = b1[tid];
    const float* w = W1 + (size_t)(2*LS)*HID + tid;   // rows 512..1151
    #pragma unroll 4
    for (int d = 0; d < 2*LW + LY; d++)
        acc += wy[d] * w[(size_t)d * HID];
    d_wyW[(b*M + m)*HID + tid] = acc;
}

// ---------------- s = exp(i*phi); write output slice -----------------------
__global__ void k_s(float* __restrict__ out, int step) {
    int b = blockIdx.x, i = threadIdx.x;
    int idx = b*LS + i;
    float p = d_phi[idx];
    float sn, cs;
    sincosf(p, &sn, &cs);
    d_sre[idx] = cs;
    d_sim[idx] = sn;
    out[(b*(NSTEP+1) + step)*LS + i] = cs;                              // s_real
    out[(size_t)B*(NSTEP+1)*LS + (b*(NSTEP+1) + step)*LS + i] = sn;     // s_imag
}

// ---------------- dominant kernel: Gs/Hs complex matvecs -------------------
// warp per (b,i) row; lanes stride j; float4 = the 4 contiguous m-values
__global__ void __launch_bounds__(256) k_mv(const float* __restrict__ Gr, const float* __restrict__ Gi,
                                            const float* __restrict__ Hr, const float* __restrict__ Hi) {
    int b     = blockIdx.x >> 5;
    int chunk = blockIdx.x & 31;
    int tid   = threadIdx.x;
    int warp  = tid >> 5, lane = tid & 31;
    int i     = chunk*8 + warp;

    __shared__ float ssr[LS], ssi[LS];
    ssr[tid] = d_sre[b*LS + tid];
    ssi[tid] = d_sim[b*LS + tid];
    __syncthreads();

    size_t base = (size_t)(b*LS + i) * (LS*M);
    float gsr[4] = {0,0,0,0}, gsi[4] = {0,0,0,0};
    float hsr[4] = {0,0,0,0}, hsi[4] = {0,0,0,0};

    #pragma unroll
    for (int t = 0; t < 8; t++) {
        int j = lane + t*32;
        float4 g_r = *reinterpret_cast<const float4*>(Gr + base + (size_t)j*M);
        float4 g_i = *reinterpret_cast<const float4*>(Gi + base + (size_t)j*M);
        float4 h_r = *reinterpret_cast<const float4*>(Hr + base + (size_t)j*M);
        float4 h_i = *reinterpret_cast<const float4*>(Hi + base + (size_t)j*M);
        float sr = ssr[j], si = ssi[j];
        float grx[4] = {g_r.x, g_r.y, g_r.z, g_r.w};
        float gix[4] = {g_i.x, g_i.y, g_i.z, g_i.w};
        float hrx[4] = {h_r.x, h_r.y, h_r.z, h_r.w};
        float hix[4] = {h_i.x, h_i.y, h_i.z, h_i.w};
        #pragma unroll
        for (int m = 0; m < 4; m++) {
            gsr[m] += grx[m]*sr - gix[m]*si;
            gsi[m] += grx[m]*si + gix[m]*sr;
            hsr[m] += hrx[m]*sr - hix[m]*si;
            hsi[m] += hrx[m]*si + hix[m]*sr;
        }
    }
    #pragma unroll
    for (int m = 0; m < 4; m++) {
        #pragma unroll
        for (int off = 16; off; off >>= 1) {
            gsr[m] += __shfl_down_sync(0xffffffffu, gsr[m], off);
            gsi[m] += __shfl_down_sync(0xffffffffu, gsi[m], off);
            hsr[m] += __shfl_down_sync(0xffffffffu, hsr[m], off);
            hsi[m] += __shfl_down_sync(0xffffffffu, hsi[m], off);
        }
    }
    if (lane == 0) {
        int o = (b*LS + i)*M;
        #pragma unroll
        for (int m = 0; m < 4; m++) {
            d_Gsr[o+m] = gsr[m]; d_Gsi[o+m] = gsi[m];
            d_Hsr[o+m] = hsr[m]; d_Hsi[o+m] = hsi[m];
        }
    }
}

// ---------------- sGs/sHs = sum_i conj(s_i)*Gs_i  (16 block reductions) ----
__global__ void k_red() {
    int b = blockIdx.x, i = threadIdx.x;
    float sr = d_sre[b*LS + i], si = d_sim[b*LS + i];
    int o = (b*LS + i)*M;
    float v[16];
    #pragma unroll
    for (int m = 0; m < 4; m++) {
        float gr = d_Gsr[o+m], gi = d_Gsi[o+m];
        float hr = d_Hsr[o+m], hi = d_Hsi[o+m];
        v[m]      = sr*gr + si*gi;   // Re(conj(s)*Gs)
        v[4+m]    = sr*gi - si*gr;   // Im
        v[8+m]    = sr*hr + si*hi;
        v[12+m]   = sr*hi - si*hr;
    }
    __shared__ float wsum[8][16];
    int warp = i >> 5, lane = i & 31;
    #pragma unroll
    for (int q = 0; q < 16; q++) {
        #pragma unroll
        for (int off = 16; off; off >>= 1)
            v[q] += __shfl_down_sync(0xffffffffu, v[q], off);
    }
    if (lane == 0) {
        #pragma unroll
        for (int q = 0; q < 16; q++) wsum[warp][q] = v[q];
    }
    __syncthreads();
    if (i < 16) {
        float s = 0.f;
        #pragma unroll
        for (int w = 0; w < 8; w++) s += wsum[w][i];
        int m = i & 3, which = i >> 2;
        if      (which == 0) d_sGr[b*M + m] = s;
        else if (which == 1) d_sGi[b*M + m] = s;
        else if (which == 2) d_sHr[b*M + m] = s;
        else                 d_sHi[b*M + m] = s;
    }
}

// ---------------- hs = [Re(s),Im(s)] @ W1[0:512]  (4 b's per block) --------
__global__ void __launch_bounds__(HID) k_hs(const float* __restrict__ W1) {
    int bg = blockIdx.x;          // 16 blocks, 4 batches each
    int h  = threadIdx.x;
    __shared__ float sf[4][2*LS];
    for (int idx = h; idx < 4*2*LS; idx += HID) {
        int bb = idx >> 9, d = idx & 511;
        int b  = bg*4 + bb;
        sf[bb][d] = (d < LS) ? d_sre[b*LS + d] : d_sim[b*LS + d - LS];
    }
    __syncthreads();
    float a0 = 0.f, a1 = 0.f, a2 = 0.f, a3 = 0.f;
    #pragma unroll 2
    for (int i = 0; i < LS; i++) {
        float w0 = W1[(size_t)i*HID + h];
        float w1 = W1[(size_t)(LS + i)*HID + h];
        a0 += sf[0][i]*w0 + sf[0][LS+i]*w1;
        a1 += sf[1][i]*w0 + sf[1][LS+i]*w1;
        a2 += sf[2][i]*w0 + sf[2][LS+i]*w1;
        a3 += sf[3][i]*w0 + sf[3][LS+i]*w1;
    }
    d_hs[(bg*4+0)*HID + h] = a0;
    d_hs[(bg*4+1)*HID + h] = a1;
    d_hs[(bg*4+2)*HID + h] = a2;
    d_hs[(bg*4+3)*HID + h] = a3;
}

// ---------------- BN stats over batch axis ---------------------------------
__global__ void k_stats(const float* __restrict__ gamma) {
    int g = blockIdx.x*256 + threadIdx.x;   // 0..2047 = (m,h)
    int m = g >> 9, h = g & 511;
    float sum = 0.f, sq = 0.f;
    for (int b = 0; b < B; b++) {
        float v = d_hs[b*HID + h] + d_wyW[(b*M + m)*HID + h];
        sum += v; sq += v*v;
    }
    float mu  = sum * (1.0f/B);
    float var = sq * (1.0f/B) - mu*mu;
    d_mu[g]    = mu;
    d_scale[g] = gamma[h] * rsqrtf(var + 1e-5f);
}

// ---------------- BN + relu + dot(W2) + sigmoid -> rho ---------------------
__global__ void __launch_bounds__(HID) k_rho(const float* __restrict__ beta, const float* __restrict__ W2,
                                             const float* __restrict__ b2, float* __restrict__ out, int step) {
    int m = blockIdx.x, b = blockIdx.y;
    int h = threadIdx.x;
    float v  = d_hs[b*HID + h] + d_wyW[(b*M + m)*HID + h];
    int g = m*HID + h;
    float bn = d_scale[g] * (v - d_mu[g]) + beta[h];
    float r  = fmaxf(bn, 0.f) * W2[h];
    #pragma unroll
    for (int off = 16; off; off >>= 1)
        r += __shfl_down_sync(0xffffffffu, r, off);
    __shared__ float ws[16];
    int warp = h >> 5, lane = h & 31;
    if (lane == 0) ws[warp] = r;
    __syncthreads();
    if (h == 0) {
        float s = 0.f;
        #pragma unroll
        for (int w = 0; w < 16; w++) s += ws[w];
        float rho = 1.0f / (1.0f + expf(-(s + b2[0])));
        d_rho[b*M + m] = rho;
        out[(size_t)2*B*(NSTEP+1)*LS + (b*NSTEP + step)*M + m] = rho;
    }
}

// ---------------- eta + phi update ------------------------------------------
__global__ void k_phi() {
    int b = blockIdx.x, i = threadIdx.x;
    __shared__ float sgr[4], sgi[4], shr_[4], shi_[4], rh[4], fac[4];
    if (i < 4) {
        float c = d_sHr[b*M + i], d = d_sHi[b*M + i];
        sgr[i] = d_sGr[b*M + i]; sgi[i] = d_sGi[b*M + i];
        shr_[i] = c; shi_[i] = d;
        rh[i] = d_rho[b*M + i];
        float zr = c*c - d*d, zi = 2.f*c*d;
        fac[i] = 2.f*zr / (zr*zr + zi*zi);   // Re(2 / sHs^2)
    }
    __syncthreads();
    float sr = d_sre[b*LS + i], si = d_sim[b*LS + i];
    int o = (b*LS + i)*M;
    float etanet = 0.f;
    #pragma unroll
    for (int m = 0; m < 4; m++) {
        float gr = d_Gsr[o+m], gi = d_Gsi[o+m];
        float hr = d_Hsr[o+m], hi = d_Hsi[o+m];
        float Ar = shr_[m]*gr - shi_[m]*gi - (sgr[m]*hr - sgi[m]*hi);
        float Ai = shr_[m]*gi + shi_[m]*gr - (sgr[m]*hi + sgi[m]*hr);
        float imnum = Ai*sr - Ar*si;         // Im(A * conj(s))
        etanet += fac[m] * imnum * rh[m];
    }
    d_phi[b*LS + i] -= etanet;
}

// ---------------- launch -----------------------------------------------------
extern "C" void kernel_launch(void* const* d_in, const int* in_sizes, int n_in,
                              void* d_out, int out_size) {
    const float* phi   = (const float*)d_in[0];
    const float* wr    = (const float*)d_in[1];
    const float* wi    = (const float*)d_in[2];
    const float* y     = (const float*)d_in[3];
    const float* Gr    = (const float*)d_in[4];
    const float* Gi    = (const float*)d_in[5];
    const float* Hr    = (const float*)d_in[6];
    const float* Hi    = (const float*)d_in[7];
    const float* W1    = (const float*)d_in[8];
    const float* b1    = (const float*)d_in[9];
    const float* gamma = (const float*)d_in[10];
    const float* beta  = (const float*)d_in[11];
    const float* W2    = (const float*)d_in[12];
    const float* b2    = (const float*)d_in[13];
    float* out = (float*)d_out;

    k_init<<<B, LS>>>(phi);
    k_wyW<<<dim3(M, B), HID>>>(wr, wi, y, W1, b1);
    for (int step = 0; step < NSTEP; step++) {
        k_s<<<B, LS>>>(out, step);
        k_mv<<<B*(LS/8), 256>>>(Gr, Gi, Hr, Hi);
        k_red<<<B, LS>>>();
        k_hs<<<16, HID>>>(W1);
        k_stats<<<8, 256>>>(gamma);
        k_rho<<<dim3(M, B), HID>>>(beta, W2, b2, out, step);
        k_phi<<<B, LS>>>();
    }
    k_s<<<B, LS>>>(out, NSTEP);
}

// round 2
// speedup vs baseline: 1.7050x; 1.7050x over previous
#include <cuda_runtime.h>
#include <math.h>

#define B 64
#define LS 256
#define M 4
#define LW 256
#define LY 128
#define HID 512
#define NSTEP 6
#define NS1 (NSTEP+1)

// ---------------- scratch (__device__ globals: no allocs allowed) ----------
__device__ float d_phi[B*LS];
__device__ float d_sre[B*LS];
__device__ float d_sim[B*LS];
__device__ float d_Gsr[B*LS*M];
__device__ float d_Gsi[B*LS*M];
__device__ float d_Hsr[B*LS*M];
__device__ float d_Hsi[B*LS*M];
__device__ float d_sGr[B*M];
__device__ float d_sGi[B*M];
__device__ float d_sHr[B*M];
__device__ float d_sHi[B*M];
__device__ float d_hs[B*HID];
__device__ float d_wyW[B*M*HID];
__device__ float d_mu[M*HID];
__device__ float d_scale[M*HID];

// ---------------- pre: copy phi, s0 = exp(i*phi), write out slice 0 --------
__global__ void k_pre(const float* __restrict__ phi, float* __restrict__ out) {
    int b = blockIdx.x, i = threadIdx.x;
    int idx = b*LS + i;
    float p = phi[idx];
    d_phi[idx] = p;
    float sn, cs;
    sincosf(p, &sn, &cs);
    d_sre[idx] = cs;
    d_sim[idx] = sn;
    out[(b*NS1)*LS + i] = cs;
    out[(size_t)B*NS1*LS + (b*NS1)*LS + i] = sn;
}

// ---------------- precompute wy @ W1[512:] + b1 (step-invariant) -----------
// one block per b; each thread h accumulates all 4 m targets
__global__ void __launch_bounds__(HID) k_wyW(const float* __restrict__ wr, const float* __restrict__ wi,
                                             const float* __restrict__ y,  const float* __restrict__ W1,
                                             const float* __restrict__ b1) {
    int b = blockIdx.x;
    int tid = threadIdx.x;                 // h
    __shared__ float4 wy[2*LW + LY];       // 640 x 4 m-values
    for (int d = tid; d < 2*LW + LY; d += HID) {
        float4 v;
        if (d < LW)            v = *reinterpret_cast<const float4*>(wr + (size_t)(b*LW + d)*M);
        else if (d < 2*LW)     v = *reinterpret_cast<const float4*>(wi + (size_t)(b*LW + (d - LW))*M);
        else                   v = *reinterpret_cast<const float4*>(y  + (size_t)(b*LY + (d - 2*LW))*M);
        wy[d] = v;
    }
    __syncthreads();
    float bb = b1[tid];
    float a0 = bb, a1 = bb, a2 = bb, a3 = bb;
    const float* w = W1 + (size_t)(2*LS)*HID + tid;   // rows 512..1151
    #pragma unroll 4
    for (int d = 0; d < 2*LW + LY; d++) {
        float wv = w[(size_t)d * HID];
        float4 q = wy[d];
        a0 += q.x*wv; a1 += q.y*wv; a2 += q.z*wv; a3 += q.w*wv;
    }
    d_wyW[(b*M + 0)*HID + tid] = a0;
    d_wyW[(b*M + 1)*HID + tid] = a1;
    d_wyW[(b*M + 2)*HID + tid] = a2;
    d_wyW[(b*M + 3)*HID + tid] = a3;
}

// ---------------- dominant kernel: Gs/Hs complex matvecs -------------------
__global__ void __launch_bounds__(256) k_mv(const float* __restrict__ Gr, const float* __restrict__ Gi,
                                            const float* __restrict__ Hr, const float* __restrict__ Hi) {
    int b     = blockIdx.x >> 5;
    int chunk = blockIdx.x & 31;
    int tid   = threadIdx.x;
    int warp  = tid >> 5, lane = tid & 31;
    int i     = chunk*8 + warp;

    __shared__ float ssr[LS], ssi[LS];
    ssr[tid] = d_sre[b*LS + tid];
    ssi[tid] = d_sim[b*LS + tid];
    __syncthreads();

    size_t base = (size_t)(b*LS + i) * (LS*M);
    float gsr[4] = {0,0,0,0}, gsi[4] = {0,0,0,0};
    float hsr[4] = {0,0,0,0}, hsi[4] = {0,0,0,0};

    #pragma unroll
    for (int t = 0; t < 8; t++) {
        int j = lane + t*32;
        float4 g_r = __ldcs(reinterpret_cast<const float4*>(Gr + base + (size_t)j*M));
        float4 g_i = __ldcs(reinterpret_cast<const float4*>(Gi + base + (size_t)j*M));
        float4 h_r = __ldcs(reinterpret_cast<const float4*>(Hr + base + (size_t)j*M));
        float4 h_i = __ldcs(reinterpret_cast<const float4*>(Hi + base + (size_t)j*M));
        float sr = ssr[j], si = ssi[j];
        float grx[4] = {g_r.x, g_r.y, g_r.z, g_r.w};
        float gix[4] = {g_i.x, g_i.y, g_i.z, g_i.w};
        float hrx[4] = {h_r.x, h_r.y, h_r.z, h_r.w};
        float hix[4] = {h_i.x, h_i.y, h_i.z, h_i.w};
        #pragma unroll
        for (int m = 0; m < 4; m++) {
            gsr[m] += grx[m]*sr - gix[m]*si;
            gsi[m] += grx[m]*si + gix[m]*sr;
            hsr[m] += hrx[m]*sr - hix[m]*si;
            hsi[m] += hrx[m]*si + hix[m]*sr;
        }
    }
    #pragma unroll
    for (int m = 0; m < 4; m++) {
        #pragma unroll
        for (int off = 16; off; off >>= 1) {
            gsr[m] += __shfl_down_sync(0xffffffffu, gsr[m], off);
            gsi[m] += __shfl_down_sync(0xffffffffu, gsi[m], off);
            hsr[m] += __shfl_down_sync(0xffffffffu, hsr[m], off);
            hsi[m] += __shfl_down_sync(0xffffffffu, hsi[m], off);
        }
    }
    if (lane == 0) {
        int o = (b*LS + i)*M;
        #pragma unroll
        for (int m = 0; m < 4; m++) {
            d_Gsr[o+m] = gsr[m]; d_Gsi[o+m] = gsi[m];
            d_Hsr[o+m] = hsr[m]; d_Hsi[o+m] = hsi[m];
        }
    }
}

// ---------------- fused: sGs/sHs reduction + hs = s_feat @ W1[0:512] -------
// one block per b, 512 threads
__global__ void __launch_bounds__(HID) k_mid(const float* __restrict__ W1) {
    int b = blockIdx.x, tid = threadIdx.x;
    __shared__ float ssr[LS], ssi[LS];
    __shared__ float wsum[8][16];
    if (tid < LS) ssr[tid] = d_sre[b*LS + tid];
    else          ssi[tid - LS] = d_sim[b*LS + tid - LS];
    __syncthreads();

    // --- red part (warps 0..7, one i per thread) ---
    if (tid < LS) {
        int i = tid, o = (b*LS + i)*M;
        int warp = tid >> 5, lane = tid & 31;
        float4 g_r = *reinterpret_cast<const float4*>(d_Gsr + o);
        float4 g_i = *reinterpret_cast<const float4*>(d_Gsi + o);
        float4 h_r = *reinterpret_cast<const float4*>(d_Hsr + o);
        float4 h_i = *reinterpret_cast<const float4*>(d_Hsi + o);
        float sr = ssr[i], si = ssi[i];
        float grx[4] = {g_r.x, g_r.y, g_r.z, g_r.w};
        float gix[4] = {g_i.x, g_i.y, g_i.z, g_i.w};
        float hrx[4] = {h_r.x, h_r.y, h_r.z, h_r.w};
        float hix[4] = {h_i.x, h_i.y, h_i.z, h_i.w};
        float v[16];
        #pragma unroll
        for (int m = 0; m < 4; m++) {
            v[m]    = sr*grx[m] + si*gix[m];   // Re(conj(s)*Gs)
            v[4+m]  = sr*gix[m] - si*grx[m];   // Im
            v[8+m]  = sr*hrx[m] + si*hix[m];
            v[12+m] = sr*hix[m] - si*hrx[m];
        }
        #pragma unroll
        for (int q = 0; q < 16; q++) {
            #pragma unroll
            for (int off = 16; off; off >>= 1)
                v[q] += __shfl_down_sync(0xffffffffu, v[q], off);
        }
        if (lane == 0) {
            #pragma unroll
            for (int q = 0; q < 16; q++) wsum[warp][q] = v[q];
        }
    }

    // --- hs part (all 512 threads, h = tid) ---
    float a = 0.f;
    #pragma unroll 2
    for (int i = 0; i < LS; i++) {
        float w0 = W1[(size_t)i*HID + tid];
        float w1 = W1[(size_t)(LS + i)*HID + tid];
        a += ssr[i]*w0 + ssi[i]*w1;
    }
    d_hs[b*HID + tid] = a;

    __syncthreads();
    if (tid < 16) {
        float s = 0.f;
        #pragma unroll
        for (int w = 0; w < 8; w++) s += wsum[w][tid];
        int m = tid & 3, which = tid >> 2;
        if      (which == 0) d_sGr[b*M + m] = s;
        else if (which == 1) d_sGi[b*M + m] = s;
        else if (which == 2) d_sHr[b*M + m] = s;
        else                 d_sHi[b*M + m] = s;
    }
}

// ---------------- BN stats over batch axis ---------------------------------
__global__ void k_stats(const float* __restrict__ gamma) {
    int g = blockIdx.x*256 + threadIdx.x;   // 0..2047 = (m,h)
    int m = g >> 9, h = g & 511;
    float sum = 0.f, sq = 0.f;
    #pragma unroll 4
    for (int b = 0; b < B; b++) {
        float v = d_hs[b*HID + h] + d_wyW[(b*M + m)*HID + h];
        sum += v; sq += v*v;
    }
    float mu  = sum * (1.0f/B);
    float var = sq * (1.0f/B) - mu*mu;
    d_mu[g]    = mu;
    d_scale[g] = gamma[h] * rsqrtf(var + 1e-5f);
}

// ---------------- fused: BN+relu+W2+sigmoid -> rho; eta; phi; next s -------
// one block per b, 512 threads
__global__ void __launch_bounds__(HID) k_fin(const float* __restrict__ beta, const float* __restrict__ W2,
                                             const float* __restrict__ b2, float* __restrict__ out, int step) {
    int b = blockIdx.x, tid = threadIdx.x;
    int warp = tid >> 5, lane = tid & 31;
    __shared__ float ws[16][4];
    __shared__ float rho_s[4], fac[4], sgr[4], sgi[4], shr_[4], shi_[4];

    float hsv = d_hs[b*HID + tid];
    float bt  = beta[tid];
    float w2  = W2[tid];
    float r[4];
    #pragma unroll
    for (int m = 0; m < 4; m++) {
        float v  = hsv + d_wyW[(b*M + m)*HID + tid];
        int g = m*HID + tid;
        float bn = d_scale[g] * (v - d_mu[g]) + bt;
        r[m] = fmaxf(bn, 0.f) * w2;
    }
    #pragma unroll
    for (int m = 0; m < 4; m++) {
        #pragma unroll
        for (int off = 16; off; off >>= 1)
            r[m] += __shfl_down_sync(0xffffffffu, r[m], off);
    }
    if (lane == 0) {
        #pragma unroll
        for (int m = 0; m < 4; m++) ws[warp][m] = r[m];
    }
    __syncthreads();
    if (tid < 4) {
        float s = 0.f;
        #pragma unroll
        for (int w = 0; w < 16; w++) s += ws[w][tid];
        float rho = 1.0f / (1.0f + expf(-(s + b2[0])));
        rho_s[tid] = rho;
        out[(size_t)2*B*NS1*LS + (b*NSTEP + step)*M + tid] = rho;
        float c = d_sHr[b*M + tid], d = d_sHi[b*M + tid];
        sgr[tid] = d_sGr[b*M + tid]; sgi[tid] = d_sGi[b*M + tid];
        shr_[tid] = c; shi_[tid] = d;
        float zr = c*c - d*d, zi = 2.f*c*d;
        fac[tid] = 2.f*zr / (zr*zr + zi*zi);   // Re(2 / sHs^2)
    }
    __syncthreads();

    if (tid < LS) {
        int i = tid, idx = b*LS + i, o = idx*M;
        float sr = d_sre[idx], si = d_sim[idx];
        float4 g_r = *reinterpret_cast<const float4*>(d_Gsr + o);
        float4 g_i = *reinterpret_cast<const float4*>(d_Gsi + o);
        float4 h_r = *reinterpret_cast<const float4*>(d_Hsr + o);
        float4 h_i = *reinterpret_cast<const float4*>(d_Hsi + o);
        float grx[4] = {g_r.x, g_r.y, g_r.z, g_r.w};
        float gix[4] = {g_i.x, g_i.y, g_i.z, g_i.w};
        float hrx[4] = {h_r.x, h_r.y, h_r.z, h_r.w};
        float hix[4] = {h_i.x, h_i.y, h_i.z, h_i.w};
        float etanet = 0.f;
        #pragma unroll
        for (int m = 0; m < 4; m++) {
            float Ar = shr_[m]*grx[m] - shi_[m]*gix[m] - (sgr[m]*hrx[m] - sgi[m]*hix[m]);
            float Ai = shr_[m]*gix[m] + shi_[m]*grx[m] - (sgr[m]*hix[m] + sgi[m]*hrx[m]);
            float imnum = Ai*sr - Ar*si;       // Im(A * conj(s))
            etanet += fac[m] * imnum * rho_s[m];
        }
        float p = d_phi[idx] - etanet;
        d_phi[idx] = p;
        float sn, cs;
        sincosf(p, &sn, &cs);
        d_sre[idx] = cs;
        d_sim[idx] = sn;
        out[(b*NS1 + step + 1)*LS + i] = cs;
        out[(size_t)B*NS1*LS + (b*NS1 + step + 1)*LS + i] = sn;
    }
}

// ---------------- launch -----------------------------------------------------
extern "C" void kernel_launch(void* const* d_in, const int* in_sizes, int n_in,
                              void* d_out, int out_size) {
    const float* phi   = (const float*)d_in[0];
    const float* wr    = (const float*)d_in[1];
    const float* wi    = (const float*)d_in[2];
    const float* y     = (const float*)d_in[3];
    const float* Gr    = (const float*)d_in[4];
    const float* Gi    = (const float*)d_in[5];
    const float* Hr    = (const float*)d_in[6];
    const float* Hi    = (const float*)d_in[7];
    const float* W1    = (const float*)d_in[8];
    const float* b1    = (const float*)d_in[9];
    const float* gamma = (const float*)d_in[10];
    const float* beta  = (const float*)d_in[11];
    const float* W2    = (const float*)d_in[12];
    const float* b2    = (const float*)d_in[13];
    float* out = (float*)d_out;

    k_pre<<<B, LS>>>(phi, out);
    k_wyW<<<B, HID>>>(wr, wi, y, W1, b1);
    for (int step = 0; step < NSTEP; step++) {
        k_mv<<<B*(LS/8), 256>>>(Gr, Gi, Hr, Hi);
        k_mid<<<B, HID>>>(W1);
        k_stats<<<8, 256>>>(gamma);
        k_fin<<<B, HID>>>(beta, W2, b2, out, step);
    }
}

// round 3
// speedup vs baseline: 2.1638x; 1.2691x over previous
#include <cuda_runtime.h>
#include <math.h>

#define B 64
#define LS 256
#define M 4
#define LW 256
#define LY 128
#define HID 512
#define NSTEP 6
#define NS1 (NSTEP+1)
#define KC 8          // split-K chunks for k_hs

// ---------------- scratch (__device__ globals: no allocs allowed) ----------
__device__ float d_phi[B*LS];
__device__ float d_sre[B*LS];
__device__ float d_sim[B*LS];
__device__ float d_Gsr[B*LS*M];
__device__ float d_Gsi[B*LS*M];
__device__ float d_Hsr[B*LS*M];
__device__ float d_Hsi[B*LS*M];
__device__ float d_hsp[KC*B*HID];    // split-K partials of hs
__device__ float d_wyW[B*M*HID];
__device__ float d_mu[M*HID];
__device__ float d_scale[M*HID];

// ---------------- pre: copy phi, s0 = exp(i*phi), write out slice 0 --------
__global__ void k_pre(const float* __restrict__ phi, float* __restrict__ out) {
    int b = blockIdx.x, i = threadIdx.x;
    int idx = b*LS + i;
    float p = phi[idx];
    d_phi[idx] = p;
    float sn, cs;
    sincosf(p, &sn, &cs);
    d_sre[idx] = cs;
    d_sim[idx] = sn;
    out[(b*NS1)*LS + i] = cs;
    out[(size_t)B*NS1*LS + (b*NS1)*LS + i] = sn;
}

// ---------------- precompute wy @ W1[512:] + b1 (step-invariant) -----------
__global__ void __launch_bounds__(HID) k_wyW(const float* __restrict__ wr, const float* __restrict__ wi,
                                             const float* __restrict__ y,  const float* __restrict__ W1,
                                             const float* __restrict__ b1) {
    int b = blockIdx.x;
    int tid = threadIdx.x;                 // h
    __shared__ float4 wy[2*LW + LY];       // 640 x 4 m-values
    for (int d = tid; d < 2*LW + LY; d += HID) {
        float4 v;
        if (d < LW)            v = *reinterpret_cast<const float4*>(wr + (size_t)(b*LW + d)*M);
        else if (d < 2*LW)     v = *reinterpret_cast<const float4*>(wi + (size_t)(b*LW + (d - LW))*M);
        else                   v = *reinterpret_cast<const float4*>(y  + (size_t)(b*LY + (d - 2*LW))*M);
        wy[d] = v;
    }
    __syncthreads();
    float bb = b1[tid];
    float a0 = bb, a1 = bb, a2 = bb, a3 = bb;
    const float* w = W1 + (size_t)(2*LS)*HID + tid;   // rows 512..1151
    #pragma unroll 4
    for (int d = 0; d < 2*LW + LY; d++) {
        float wv = w[(size_t)d * HID];
        float4 q = wy[d];
        a0 += q.x*wv; a1 += q.y*wv; a2 += q.z*wv; a3 += q.w*wv;
    }
    d_wyW[(b*M + 0)*HID + tid] = a0;
    d_wyW[(b*M + 1)*HID + tid] = a1;
    d_wyW[(b*M + 2)*HID + tid] = a2;
    d_wyW[(b*M + 3)*HID + tid] = a3;
}

// ---------------- dominant kernel: Gs/Hs complex matvecs -------------------
__global__ void __launch_bounds__(256) k_mv(const float* __restrict__ Gr, const float* __restrict__ Gi,
                                            const float* __restrict__ Hr, const float* __restrict__ Hi) {
    int b     = blockIdx.x >> 5;
    int chunk = blockIdx.x & 31;
    int tid   = threadIdx.x;
    int warp  = tid >> 5, lane = tid & 31;
    int i     = chunk*8 + warp;

    __shared__ float ssr[LS], ssi[LS];
    ssr[tid] = d_sre[b*LS + tid];
    ssi[tid] = d_sim[b*LS + tid];
    __syncthreads();

    size_t base = (size_t)(b*LS + i) * (LS*M);
    float gsr[4] = {0,0,0,0}, gsi[4] = {0,0,0,0};
    float hsr[4] = {0,0,0,0}, hsi[4] = {0,0,0,0};

    #pragma unroll
    for (int t = 0; t < 8; t++) {
        int j = lane + t*32;
        float4 g_r = __ldcs(reinterpret_cast<const float4*>(Gr + base + (size_t)j*M));
        float4 g_i = __ldcs(reinterpret_cast<const float4*>(Gi + base + (size_t)j*M));
        float4 h_r = __ldcs(reinterpret_cast<const float4*>(Hr + base + (size_t)j*M));
        float4 h_i = __ldcs(reinterpret_cast<const float4*>(Hi + base + (size_t)j*M));
        float sr = ssr[j], si = ssi[j];
        float grx[4] = {g_r.x, g_r.y, g_r.z, g_r.w};
        float gix[4] = {g_i.x, g_i.y, g_i.z, g_i.w};
        float hrx[4] = {h_r.x, h_r.y, h_r.z, h_r.w};
        float hix[4] = {h_i.x, h_i.y, h_i.z, h_i.w};
        #pragma unroll
        for (int m = 0; m < 4; m++) {
            gsr[m] += grx[m]*sr - gix[m]*si;
            gsi[m] += grx[m]*si + gix[m]*sr;
            hsr[m] += hrx[m]*sr - hix[m]*si;
            hsi[m] += hrx[m]*si + hix[m]*sr;
        }
    }
    #pragma unroll
    for (int m = 0; m < 4; m++) {
        #pragma unroll
        for (int off = 16; off; off >>= 1) {
            gsr[m] += __shfl_down_sync(0xffffffffu, gsr[m], off);
            gsi[m] += __shfl_down_sync(0xffffffffu, gsi[m], off);
            hsr[m] += __shfl_down_sync(0xffffffffu, hsr[m], off);
            hsi[m] += __shfl_down_sync(0xffffffffu, hsi[m], off);
        }
    }
    if (lane == 0) {
        int o = (b*LS + i)*M;
        #pragma unroll
        for (int m = 0; m < 4; m++) {
            d_Gsr[o+m] = gsr[m]; d_Gsi[o+m] = gsi[m];
            d_Hsr[o+m] = hsr[m]; d_Hsi[o+m] = hsi[m];
        }
    }
}

// ---------------- hs GEMM (split-K): hsp[kc][b][h] partials ----------------
// grid = 16 b-quads x 8 k-chunks; block 512 (thread = h)
__global__ void __launch_bounds__(HID) k_hs(const float* __restrict__ W1) {
    int kc = blockIdx.x & 7;
    int bq = blockIdx.x >> 3;
    int tid = threadIdx.x;
    __shared__ float sf[4][64];
    if (tid < 256) {
        int bb = tid >> 6, dd = tid & 63;
        int b = bq*4 + bb, d = kc*64 + dd;
        sf[bb][dd] = (d < LS) ? d_sre[b*LS + d] : d_sim[b*LS + d - LS];
    }
    __syncthreads();
    float a0 = 0.f, a1 = 0.f, a2 = 0.f, a3 = 0.f;
    const float* w = W1 + (size_t)(kc*64)*HID + tid;
    #pragma unroll 8
    for (int dd = 0; dd < 64; dd++) {
        float wv = w[(size_t)dd * HID];
        a0 += sf[0][dd]*wv; a1 += sf[1][dd]*wv;
        a2 += sf[2][dd]*wv; a3 += sf[3][dd]*wv;
    }
    int b0 = bq*4;
    d_hsp[(kc*B + b0+0)*HID + tid] = a0;
    d_hsp[(kc*B + b0+1)*HID + tid] = a1;
    d_hsp[(kc*B + b0+2)*HID + tid] = a2;
    d_hsp[(kc*B + b0+3)*HID + tid] = a3;
}

// ---------------- BN stats over batch axis ---------------------------------
// grid = (8 h-chunks, 4 m); block 256 = 4 b-subsets x 64 h
__global__ void k_stats(const float* __restrict__ gamma) {
    int hc = blockIdx.x, m = blockIdx.y;
    int t = threadIdx.x;
    int hh = t & 63, bs = t >> 6;
    int h = hc*64 + hh;
    float sum = 0.f, sq = 0.f;
    #pragma unroll 2
    for (int k = 0; k < 16; k++) {
        int b = bs*16 + k;
        float hv = 0.f;
        #pragma unroll
        for (int kc = 0; kc < KC; kc++)
            hv += d_hsp[(kc*B + b)*HID + h];
        float v = hv + d_wyW[(b*M + m)*HID + h];
        sum += v; sq += v*v;
    }
    __shared__ float ssum[4][64], ssq[4][64];
    ssum[bs][hh] = sum; ssq[bs][hh] = sq;
    __syncthreads();
    if (t < 64) {
        float S = ssum[0][t]+ssum[1][t]+ssum[2][t]+ssum[3][t];
        float Q = ssq[0][t]+ssq[1][t]+ssq[2][t]+ssq[3][t];
        float mu  = S * (1.0f/B);
        float var = Q * (1.0f/B) - mu*mu;
        int hg = hc*64 + t;
        d_mu[m*HID + hg]    = mu;
        d_scale[m*HID + hg] = gamma[hg] * rsqrtf(var + 1e-5f);
    }
}

// ---------------- fused: sGs/sHs red + BN+rho + eta + phi + next s ---------
// one block per b, 512 threads
__global__ void __launch_bounds__(HID) k_fin(const float* __restrict__ beta, const float* __restrict__ W2,
                                             const float* __restrict__ b2, float* __restrict__ out, int step) {
    int b = blockIdx.x, tid = threadIdx.x;
    int warp = tid >> 5, lane = tid & 31;
    __shared__ float ws[16][4];
    __shared__ float wsum[8][16];
    __shared__ float rho_s[4], fac[4], sgr[4], sgi[4], shr_[4], shi_[4];

    // --- phase 1: per-i loads + sGs/sHs warp reduction (tid < 256) ---
    float sr = 0.f, si = 0.f;
    float grx[4], gix[4], hrx[4], hix[4];
    if (tid < LS) {
        int idx = b*LS + tid, o = idx*M;
        sr = d_sre[idx]; si = d_sim[idx];
        float4 g_r = *reinterpret_cast<const float4*>(d_Gsr + o);
        float4 g_i = *reinterpret_cast<const float4*>(d_Gsi + o);
        float4 h_r = *reinterpret_cast<const float4*>(d_Hsr + o);
        float4 h_i = *reinterpret_cast<const float4*>(d_Hsi + o);
        grx[0]=g_r.x; grx[1]=g_r.y; grx[2]=g_r.z; grx[3]=g_r.w;
        gix[0]=g_i.x; gix[1]=g_i.y; gix[2]=g_i.z; gix[3]=g_i.w;
        hrx[0]=h_r.x; hrx[1]=h_r.y; hrx[2]=h_r.z; hrx[3]=h_r.w;
        hix[0]=h_i.x; hix[1]=h_i.y; hix[2]=h_i.z; hix[3]=h_i.w;
        float v[16];
        #pragma unroll
        for (int m = 0; m < 4; m++) {
            v[m]    = sr*grx[m] + si*gix[m];
            v[4+m]  = sr*gix[m] - si*grx[m];
            v[8+m]  = sr*hrx[m] + si*hix[m];
            v[12+m] = sr*hix[m] - si*hrx[m];
        }
        #pragma unroll
        for (int q = 0; q < 16; q++) {
            #pragma unroll
            for (int off = 16; off; off >>= 1)
                v[q] += __shfl_down_sync(0xffffffffu, v[q], off);
        }
        if (lane == 0) {
            #pragma unroll
            for (int q = 0; q < 16; q++) wsum[warp][q] = v[q];
        }
    }
    __syncthreads();
    if (tid < 16) {
        float s = 0.f;
        #pragma unroll
        for (int w = 0; w < 8; w++) s += wsum[w][tid];
        int m = tid & 3, which = tid >> 2;
        if      (which == 0) sgr[m] = s;
        else if (which == 1) sgi[m] = s;
        else if (which == 2) shr_[m] = s;
        else                 shi_[m] = s;
    }

    // --- phase 2: BN + relu + W2 partial dot (all 512 threads, h = tid) ---
    float hsv = 0.f;
    #pragma unroll
    for (int kc = 0; kc < KC; kc++)
        hsv += d_hsp[(kc*B + b)*HID + tid];
    float bt = beta[tid];
    float w2 = W2[tid];
    float r[4];
    #pragma unroll
    for (int m = 0; m < 4; m++) {
        float v  = hsv + d_wyW[(b*M + m)*HID + tid];
        int g = m*HID + tid;
        float bn = d_scale[g] * (v - d_mu[g]) + bt;
        r[m] = fmaxf(bn, 0.f) * w2;
    }
    #pragma unroll
    for (int m = 0; m < 4; m++) {
        #pragma unroll
        for (int off = 16; off; off >>= 1)
            r[m] += __shfl_down_sync(0xffffffffu, r[m], off);
    }
    if (lane == 0) {
        #pragma unroll
        for (int m = 0; m < 4; m++) ws[warp][m] = r[m];
    }
    __syncthreads();
    if (tid < 4) {
        float s = 0.f;
        #pragma unroll
        for (int w = 0; w < 16; w++) s += ws[w][tid];
        float rho = 1.0f / (1.0f + expf(-(s + b2[0])));
        rho_s[tid] = rho;
        out[(size_t)2*B*NS1*LS + (b*NSTEP + step)*M + tid] = rho;
        float c = shr_[tid], d = shi_[tid];
        float zr = c*c - d*d, zi = 2.f*c*d;
        fac[tid] = 2.f*zr / (zr*zr + zi*zi);   // Re(2 / sHs^2)
    }
    __syncthreads();

    // --- phase 3: eta + phi update + next s (tid < 256, regs still live) ---
    if (tid < LS) {
        int idx = b*LS + tid;
        float etanet = 0.f;
        #pragma unroll
        for (int m = 0; m < 4; m++) {
            float Ar = shr_[m]*grx[m] - shi_[m]*gix[m] - (sgr[m]*hrx[m] - sgi[m]*hix[m]);
            float Ai = shr_[m]*gix[m] + shi_[m]*grx[m] - (sgr[m]*hix[m] + sgi[m]*hrx[m]);
            float imnum = Ai*sr - Ar*si;       // Im(A * conj(s))
            etanet += fac[m] * imnum * rho_s[m];
        }
        float p = d_phi[idx] - etanet;
        d_phi[idx] = p;
        float sn, cs;
        sincosf(p, &sn, &cs);
        d_sre[idx] = cs;
        d_sim[idx] = sn;
        out[(b*NS1 + step + 1)*LS + tid] = cs;
        out[(size_t)B*NS1*LS + (b*NS1 + step + 1)*LS + tid] = sn;
    }
}

// ---------------- launch -----------------------------------------------------
extern "C" void kernel_launch(void* const* d_in, const int* in_sizes, int n_in,
                              void* d_out, int out_size) {
    const float* phi   = (const float*)d_in[0];
    const float* wr    = (const float*)d_in[1];
    const float* wi    = (const float*)d_in[2];
    const float* y     = (const float*)d_in[3];
    const float* Gr    = (const float*)d_in[4];
    const float* Gi    = (const float*)d_in[5];
    const float* Hr    = (const float*)d_in[6];
    const float* Hi    = (const float*)d_in[7];
    const float* W1    = (const float*)d_in[8];
    const float* b1    = (const float*)d_in[9];
    const float* gamma = (const float*)d_in[10];
    const float* beta  = (const float*)d_in[11];
    const float* W2    = (const float*)d_in[12];
    const float* b2    = (const float*)d_in[13];
    float* out = (float*)d_out;

    k_pre<<<B, LS>>>(phi, out);
    k_wyW<<<B, HID>>>(wr, wi, y, W1, b1);
    for (int step = 0; step < NSTEP; step++) {
        k_mv<<<B*(LS/8), 256>>>(Gr, Gi, Hr, Hi);
        k_hs<<<128, HID>>>(W1);
        k_stats<<<dim3(8,4), 256>>>(gamma);
        k_fin<<<B, HID>>>(beta, W2, b2, out, step);
    }
}

// round 4
// speedup vs baseline: 2.3286x; 1.0761x over previous
#include <cuda_runtime.h>
#include <math.h>

#define B 64
#define LS 256
#define M 4
#define LW 256
#define LY 128
#define HID 512
#define NSTEP 6
#define NS1 (NSTEP+1)
#define KC 8          // split-K chunks for hs

// ---------------- scratch (__device__ globals: no allocs allowed) ----------
__device__ float d_phi[B*LS];
__device__ float d_sre[B*LS];
__device__ float d_sim[B*LS];
__device__ float d_Gsr[B*LS*M];
__device__ float d_Gsi[B*LS*M];
__device__ float d_Hsr[B*LS*M];
__device__ float d_Hsi[B*LS*M];
__device__ float d_hsp[KC*B*HID];    // split-K partials of hs
__device__ float d_wyW[B*M*HID];
__device__ float d_mu[M*HID];
__device__ float d_scale[M*HID];

// ---------------- init: phi copy + s0 + out slice 0 + wyW precompute -------
// blocks 0..63: pre for b=blockIdx ; blocks 64..127: wyW for b=blockIdx-64
__global__ void __launch_bounds__(HID) k_init(const float* __restrict__ phi, float* __restrict__ out,
                                              const float* __restrict__ wr, const float* __restrict__ wi,
                                              const float* __restrict__ y,  const float* __restrict__ W1,
                                              const float* __restrict__ b1) {
    int tid = threadIdx.x;
    if (blockIdx.x < B) {
        int b = blockIdx.x;
        if (tid < LS) {
            int idx = b*LS + tid;
            float p = phi[idx];
            d_phi[idx] = p;
            float sn, cs;
            sincosf(p, &sn, &cs);
            d_sre[idx] = cs;
            d_sim[idx] = sn;
            out[(b*NS1)*LS + tid] = cs;
            out[(size_t)B*NS1*LS + (b*NS1)*LS + tid] = sn;
        }
        return;
    }
    int b = blockIdx.x - B;
    __shared__ float4 wy[2*LW + LY];       // 640 x 4 m-values
    for (int d = tid; d < 2*LW + LY; d += HID) {
        float4 v;
        if (d < LW)            v = *reinterpret_cast<const float4*>(wr + (size_t)(b*LW + d)*M);
        else if (d < 2*LW)     v = *reinterpret_cast<const float4*>(wi + (size_t)(b*LW + (d - LW))*M);
        else                   v = *reinterpret_cast<const float4*>(y  + (size_t)(b*LY + (d - 2*LW))*M);
        wy[d] = v;
    }
    __syncthreads();
    float bb = b1[tid];
    float a0 = bb, a1 = bb, a2 = bb, a3 = bb;
    const float* w = W1 + (size_t)(2*LS)*HID + tid;   // rows 512..1151
    #pragma unroll 4
    for (int d = 0; d < 2*LW + LY; d++) {
        float wv = w[(size_t)d * HID];
        float4 q = wy[d];
        a0 += q.x*wv; a1 += q.y*wv; a2 += q.z*wv; a3 += q.w*wv;
    }
    d_wyW[(b*M + 0)*HID + tid] = a0;
    d_wyW[(b*M + 1)*HID + tid] = a1;
    d_wyW[(b*M + 2)*HID + tid] = a2;
    d_wyW[(b*M + 3)*HID + tid] = a3;
}

// ---------------- fused dominant launch: Gs/Hs matvecs + hs GEMM -----------
// blocks 0..2047: mv (warp per (b,i) row)    blocks 2048..2175: hs split-K
__global__ void __launch_bounds__(256) k_mvhs(const float* __restrict__ Gr, const float* __restrict__ Gi,
                                              const float* __restrict__ Hr, const float* __restrict__ Hi,
                                              const float* __restrict__ W1) {
    int tid = threadIdx.x;
    if (blockIdx.x < 2048) {
        // ---- mv part ----
        int b     = blockIdx.x >> 5;
        int chunk = blockIdx.x & 31;
        int warp  = tid >> 5, lane = tid & 31;
        int i     = chunk*8 + warp;

        __shared__ float ssr[LS], ssi[LS];
        ssr[tid] = d_sre[b*LS + tid];
        ssi[tid] = d_sim[b*LS + tid];
        __syncthreads();

        size_t base = (size_t)(b*LS + i) * (LS*M);
        float gsr[4] = {0,0,0,0}, gsi[4] = {0,0,0,0};
        float hsr[4] = {0,0,0,0}, hsi[4] = {0,0,0,0};

        #pragma unroll
        for (int t = 0; t < 4; t++) {
            int j0 = lane + t*64;
            int j1 = j0 + 32;
            float4 g_r0 = __ldcs(reinterpret_cast<const float4*>(Gr + base + (size_t)j0*M));
            float4 g_i0 = __ldcs(reinterpret_cast<const float4*>(Gi + base + (size_t)j0*M));
            float4 h_r0 = __ldcs(reinterpret_cast<const float4*>(Hr + base + (size_t)j0*M));
            float4 h_i0 = __ldcs(reinterpret_cast<const float4*>(Hi + base + (size_t)j0*M));
            float4 g_r1 = __ldcs(reinterpret_cast<const float4*>(Gr + base + (size_t)j1*M));
            float4 g_i1 = __ldcs(reinterpret_cast<const float4*>(Gi + base + (size_t)j1*M));
            float4 h_r1 = __ldcs(reinterpret_cast<const float4*>(Hr + base + (size_t)j1*M));
            float4 h_i1 = __ldcs(reinterpret_cast<const float4*>(Hi + base + (size_t)j1*M));
            float sr0 = ssr[j0], si0 = ssi[j0];
            float sr1 = ssr[j1], si1 = ssi[j1];
            float gr0[4] = {g_r0.x, g_r0.y, g_r0.z, g_r0.w};
            float gi0[4] = {g_i0.x, g_i0.y, g_i0.z, g_i0.w};
            float hr0[4] = {h_r0.x, h_r0.y, h_r0.z, h_r0.w};
            float hi0[4] = {h_i0.x, h_i0.y, h_i0.z, h_i0.w};
            float gr1[4] = {g_r1.x, g_r1.y, g_r1.z, g_r1.w};
            float gi1[4] = {g_i1.x, g_i1.y, g_i1.z, g_i1.w};
            float hr1[4] = {h_r1.x, h_r1.y, h_r1.z, h_r1.w};
            float hi1[4] = {h_i1.x, h_i1.y, h_i1.z, h_i1.w};
            #pragma unroll
            for (int m = 0; m < 4; m++) {
                gsr[m] += gr0[m]*sr0 - gi0[m]*si0;
                gsi[m] += gr0[m]*si0 + gi0[m]*sr0;
                hsr[m] += hr0[m]*sr0 - hi0[m]*si0;
                hsi[m] += hr0[m]*si0 + hi0[m]*sr0;
                gsr[m] += gr1[m]*sr1 - gi1[m]*si1;
                gsi[m] += gr1[m]*si1 + gi1[m]*sr1;
                hsr[m] += hr1[m]*sr1 - hi1[m]*si1;
                hsi[m] += hr1[m]*si1 + hi1[m]*sr1;
            }
        }
        #pragma unroll
        for (int m = 0; m < 4; m++) {
            #pragma unroll
            for (int off = 16; off; off >>= 1) {
                gsr[m] += __shfl_down_sync(0xffffffffu, gsr[m], off);
                gsi[m] += __shfl_down_sync(0xffffffffu, gsi[m], off);
                hsr[m] += __shfl_down_sync(0xffffffffu, hsr[m], off);
                hsi[m] += __shfl_down_sync(0xffffffffu, hsi[m], off);
            }
        }
        if (lane == 0) {
            int o = (b*LS + i)*M;
            #pragma unroll
            for (int m = 0; m < 4; m++) {
                d_Gsr[o+m] = gsr[m]; d_Gsi[o+m] = gsi[m];
                d_Hsr[o+m] = hsr[m]; d_Hsi[o+m] = hsi[m];
            }
        }
        return;
    }
    // ---- hs part: hsp[kc][b][h] split-K partials (256 thr, 2 h each) ----
    {
        int bid = blockIdx.x - 2048;    // 0..127
        int kc = bid & 7, bq = bid >> 3;
        __shared__ float sf[4][64];
        {
            int bb = tid >> 6, dd = tid & 63;
            int b = bq*4 + bb, d = kc*64 + dd;
            sf[bb][dd] = (d < LS) ? d_sre[b*LS + d] : d_sim[b*LS + d - LS];
        }
        __syncthreads();
        float a0=0.f,a1=0.f,a2=0.f,a3=0.f;
        float c0=0.f,c1=0.f,c2=0.f,c3=0.f;
        const float* w = W1 + (size_t)(kc*64)*HID + tid;
        #pragma unroll 8
        for (int dd = 0; dd < 64; dd++) {
            float wv0 = w[(size_t)dd * HID];
            float wv1 = w[(size_t)dd * HID + 256];
            float s0 = sf[0][dd], s1 = sf[1][dd], s2 = sf[2][dd], s3 = sf[3][dd];
            a0 += s0*wv0; a1 += s1*wv0; a2 += s2*wv0; a3 += s3*wv0;
            c0 += s0*wv1; c1 += s1*wv1; c2 += s2*wv1; c3 += s3*wv1;
        }
        int b0 = bq*4;
        d_hsp[(kc*B + b0+0)*HID + tid] = a0;
        d_hsp[(kc*B + b0+1)*HID + tid] = a1;
        d_hsp[(kc*B + b0+2)*HID + tid] = a2;
        d_hsp[(kc*B + b0+3)*HID + tid] = a3;
        d_hsp[(kc*B + b0+0)*HID + tid + 256] = c0;
        d_hsp[(kc*B + b0+1)*HID + tid + 256] = c1;
        d_hsp[(kc*B + b0+2)*HID + tid + 256] = c2;
        d_hsp[(kc*B + b0+3)*HID + tid + 256] = c3;
    }
}

// ---------------- BN stats over batch axis ---------------------------------
// grid = (8 h-chunks, 4 m); block 256 = 4 b-subsets x 64 h
__global__ void k_stats(const float* __restrict__ gamma) {
    int hc = blockIdx.x, m = blockIdx.y;
    int t = threadIdx.x;
    int hh = t & 63, bs = t >> 6;
    int h = hc*64 + hh;
    float sum = 0.f, sq = 0.f;
    #pragma unroll 2
    for (int k = 0; k < 16; k++) {
        int b = bs*16 + k;
        float hv = 0.f;
        #pragma unroll
        for (int kc = 0; kc < KC; kc++)
            hv += d_hsp[(kc*B + b)*HID + h];
        float v = hv + d_wyW[(b*M + m)*HID + h];
        sum += v; sq += v*v;
    }
    __shared__ float ssum[4][64], ssq[4][64];
    ssum[bs][hh] = sum; ssq[bs][hh] = sq;
    __syncthreads();
    if (t < 64) {
        float S = ssum[0][t]+ssum[1][t]+ssum[2][t]+ssum[3][t];
        float Q = ssq[0][t]+ssq[1][t]+ssq[2][t]+ssq[3][t];
        float mu  = S * (1.0f/B);
        float var = Q * (1.0f/B) - mu*mu;
        int hg = hc*64 + t;
        d_mu[m*HID + hg]    = mu;
        d_scale[m*HID + hg] = gamma[hg] * rsqrtf(var + 1e-5f);
    }
}

// ---------------- fused: sGs/sHs red + BN+rho + eta + phi + next s ---------
// one block per b, 512 threads
__global__ void __launch_bounds__(HID) k_fin(const float* __restrict__ beta, const float* __restrict__ W2,
                                             const float* __restrict__ b2, float* __restrict__ out, int step) {
    int b = blockIdx.x, tid = threadIdx.x;
    int warp = tid >> 5, lane = tid & 31;
    __shared__ float ws[16][4];
    __shared__ float wsum[8][16];
    __shared__ float rho_s[4], fac[4], sgr[4], sgi[4], shr_[4], shi_[4];

    // --- phase 1: per-i loads + sGs/sHs warp reduction (tid < 256) ---
    float sr = 0.f, si = 0.f;
    float grx[4], gix[4], hrx[4], hix[4];
    if (tid < LS) {
        int idx = b*LS + tid, o = idx*M;
        sr = d_sre[idx]; si = d_sim[idx];
        float4 g_r = *reinterpret_cast<const float4*>(d_Gsr + o);
        float4 g_i = *reinterpret_cast<const float4*>(d_Gsi + o);
        float4 h_r = *reinterpret_cast<const float4*>(d_Hsr + o);
        float4 h_i = *reinterpret_cast<const float4*>(d_Hsi + o);
        grx[0]=g_r.x; grx[1]=g_r.y; grx[2]=g_r.z; grx[3]=g_r.w;
        gix[0]=g_i.x; gix[1]=g_i.y; gix[2]=g_i.z; gix[3]=g_i.w;
        hrx[0]=h_r.x; hrx[1]=h_r.y; hrx[2]=h_r.z; hrx[3]=h_r.w;
        hix[0]=h_i.x; hix[1]=h_i.y; hix[2]=h_i.z; hix[3]=h_i.w;
        float v[16];
        #pragma unroll
        for (int m = 0; m < 4; m++) {
            v[m]    = sr*grx[m] + si*gix[m];
            v[4+m]  = sr*gix[m] - si*grx[m];
            v[8+m]  = sr*hrx[m] + si*hix[m];
            v[12+m] = sr*hix[m] - si*hrx[m];
        }
        #pragma unroll
        for (int q = 0; q < 16; q++) {
            #pragma unroll
            for (int off = 16; off; off >>= 1)
                v[q] += __shfl_down_sync(0xffffffffu, v[q], off);
        }
        if (lane == 0) {
            #pragma unroll
            for (int q = 0; q < 16; q++) wsum[warp][q] = v[q];
        }
    }
    __syncthreads();
    if (tid < 16) {
        float s = 0.f;
        #pragma unroll
        for (int w = 0; w < 8; w++) s += wsum[w][tid];
        int m = tid & 3, which = tid >> 2;
        if      (which == 0) sgr[m] = s;
        else if (which == 1) sgi[m] = s;
        else if (which == 2) shr_[m] = s;
        else                 shi_[m] = s;
    }

    // --- phase 2: BN + relu + W2 partial dot (all 512 threads, h = tid) ---
    float hsv = 0.f;
    #pragma unroll
    for (int kc = 0; kc < KC; kc++)
        hsv += d_hsp[(kc*B + b)*HID + tid];
    float bt = beta[tid];
    float w2 = W2[tid];
    float r[4];
    #pragma unroll
    for (int m = 0; m < 4; m++) {
        float v  = hsv + d_wyW[(b*M + m)*HID + tid];
        int g = m*HID + tid;
        float bn = d_scale[g] * (v - d_mu[g]) + bt;
        r[m] = fmaxf(bn, 0.f) * w2;
    }
    #pragma unroll
    for (int m = 0; m < 4; m++) {
        #pragma unroll
        for (int off = 16; off; off >>= 1)
            r[m] += __shfl_down_sync(0xffffffffu, r[m], off);
    }
    if (lane == 0) {
        #pragma unroll
        for (int m = 0; m < 4; m++) ws[warp][m] = r[m];
    }
    __syncthreads();
    if (tid < 4) {
        float s = 0.f;
        #pragma unroll
        for (int w = 0; w < 16; w++) s += ws[w][tid];
        float rho = 1.0f / (1.0f + expf(-(s + b2[0])));
        rho_s[tid] = rho;
        out[(size_t)2*B*NS1*LS + (b*NSTEP + step)*M + tid] = rho;
        float c = shr_[tid], d = shi_[tid];
        float zr = c*c - d*d, zi = 2.f*c*d;
        fac[tid] = 2.f*zr / (zr*zr + zi*zi);   // Re(2 / sHs^2)
    }
    __syncthreads();

    // --- phase 3: eta + phi update + next s (tid < 256, regs still live) ---
    if (tid < LS) {
        int idx = b*LS + tid;
        float etanet = 0.f;
        #pragma unroll
        for (int m = 0; m < 4; m++) {
            float Ar = shr_[m]*grx[m] - shi_[m]*gix[m] - (sgr[m]*hrx[m] - sgi[m]*hix[m]);
            float Ai = shr_[m]*gix[m] + shi_[m]*grx[m] - (sgr[m]*hix[m] + sgi[m]*hrx[m]);
            float imnum = Ai*sr - Ar*si;       // Im(A * conj(s))
            etanet += fac[m] * imnum * rho_s[m];
        }
        float p = d_phi[idx] - etanet;
        d_phi[idx] = p;
        float sn, cs;
        sincosf(p, &sn, &cs);
        d_sre[idx] = cs;
        d_sim[idx] = sn;
        out[(b*NS1 + step + 1)*LS + tid] = cs;
        out[(size_t)B*NS1*LS + (b*NS1 + step + 1)*LS + tid] = sn;
    }
}

// ---------------- launch -----------------------------------------------------
extern "C" void kernel_launch(void* const* d_in, const int* in_sizes, int n_in,
                              void* d_out, int out_size) {
    const float* phi   = (const float*)d_in[0];
    const float* wr    = (const float*)d_in[1];
    const float* wi    = (const float*)d_in[2];
    const float* y     = (const float*)d_in[3];
    const float* Gr    = (const float*)d_in[4];
    const float* Gi    = (const float*)d_in[5];
    const float* Hr    = (const float*)d_in[6];
    const float* Hi    = (const float*)d_in[7];
    const float* W1    = (const float*)d_in[8];
    const float* b1    = (const float*)d_in[9];
    const float* gamma = (const float*)d_in[10];
    const float* beta  = (const float*)d_in[11];
    const float* W2    = (const float*)d_in[12];
    const float* b2    = (const float*)d_in[13];
    float* out = (float*)d_out;

    k_init<<<2*B, HID>>>(phi, out, wr, wi, y, W1, b1);
    for (int step = 0; step < NSTEP; step++) {
        k_mvhs<<<2048 + 128, 256>>>(Gr, Gi, Hr, Hi, W1);
        k_stats<<<dim3(8,4), 256>>>(gamma);
        k_fin<<<B, HID>>>(beta, W2, b2, out, step);
    }
}